// round 14
// baseline (speedup 1.0000x reference)
#include <cuda_runtime.h>
#include <cuda_bf16.h>
#include <math.h>
#include <stdint.h>

#define NN 50000
#define EE 800000
#define BB 256
#define DD 128
#define HH 256
#define LL 3
#define TEMP 0.2f
#define BN_EPS 1e-5f

// ---------------- scratch (device globals) ----------------
__device__ __align__(16) __nv_bfloat16 g_xb[2][(size_t)NN * DD];
__device__ __align__(16) __nv_bfloat16 g_hb[2][(size_t)NN * DD];
__device__ __align__(16) __nv_bfloat16 g_z1b[2][(size_t)NN * HH];
__device__ __align__(16) float g_agg[2][(size_t)NN * DD];
__device__ __align__(16) float g_z2[2][(size_t)NN * DD];
__device__ __align__(16) float g_statsArena[2 * LL * 2 * 512];
__device__ __align__(16) float g_pool[2 * BB * LL * DD];
__device__ __align__(16) float g_p2[2 * BB * 128];
__device__ float g_norms[2 * BB];
__device__ __align__(16) float g_W1T_hi[2 * LL * HH * DD];
__device__ __align__(16) float g_W1T_lo[2 * LL * HH * DD];
__device__ __align__(16) float g_W2T_hi[2 * LL * DD * HH];
__device__ __align__(16) float g_W2T_lo[2 * LL * DD * HH];
__device__ int g_rowptr[NN + 1];
__device__ int g_cnt[NN];
__device__ int g_col[EE];

#define ENC_W (LL * DD * HH)
#define ENC_ST (LL * 1024)

// ---------------- helpers ----------------
__device__ __forceinline__ float tf32_round(float x) {
    uint32_t u;
    asm("cvt.rna.tf32.f32 %0, %1;" : "=r"(u) : "f"(x));
    return __uint_as_float(u);
}
__device__ __forceinline__ void red_add_v4(float* p, float4 v) {
    asm volatile("red.global.add.v4.f32 [%0], {%1,%2,%3,%4};"
                 :: "l"(p), "f"(v.x), "f"(v.y), "f"(v.z), "f"(v.w) : "memory");
}
__device__ __forceinline__ void mma_tf32(float* c, const uint32_t* a, const uint32_t* b) {
    asm volatile(
        "mma.sync.aligned.m16n8k8.row.col.f32.tf32.tf32.f32 "
        "{%0,%1,%2,%3}, {%4,%5,%6,%7}, {%8,%9}, {%0,%1,%2,%3};"
        : "+f"(c[0]), "+f"(c[1]), "+f"(c[2]), "+f"(c[3])
        : "r"(a[0]), "r"(a[1]), "r"(a[2]), "r"(a[3]), "r"(b[0]), "r"(b[1]));
}
__device__ __forceinline__ float4 bf8_to_f4(uint2 u) {
    __nv_bfloat162 b0 = *reinterpret_cast<__nv_bfloat162*>(&u.x);
    __nv_bfloat162 b1 = *reinterpret_cast<__nv_bfloat162*>(&u.y);
    float2 f0 = __bfloat1622float2(b0);
    float2 f1 = __bfloat1622float2(b1);
    return make_float4(f0.x, f0.y, f1.x, f1.y);
}
__device__ __forceinline__ uint2 f4_to_bf8(float4 v) {
    __nv_bfloat162 p0 = __floats2bfloat162_rn(v.x, v.y);
    __nv_bfloat162 p1 = __floats2bfloat162_rn(v.z, v.w);
    uint2 u;
    u.x = *reinterpret_cast<uint32_t*>(&p0);
    u.y = *reinterpret_cast<uint32_t*>(&p1);
    return u;
}

// ---------------- CSR build ----------------
__global__ void count_kernel(const int* __restrict__ dst, int* __restrict__ cnt) {
    int e = blockIdx.x * blockDim.x + threadIdx.x;
    if (e < EE) atomicAdd(&cnt[dst[e]], 1);
}

__global__ void scan_kernel(const int* __restrict__ cnt, int* __restrict__ rowptr) {
    __shared__ int wsums[32];
    __shared__ int s_carry;
    int t = threadIdx.x, lane = t & 31, w = t >> 5;
    if (t == 0) s_carry = 0;
    __syncthreads();
    for (int base = 0; base < NN; base += 1024) {
        int i = base + t;
        int v = (i < NN) ? cnt[i] : 0;
        int x = v;
#pragma unroll
        for (int o = 1; o < 32; o <<= 1) {
            int y = __shfl_up_sync(0xffffffff, x, o);
            if (lane >= o) x += y;
        }
        if (lane == 31) wsums[w] = x;
        __syncthreads();
        if (w == 0) {
            int s = wsums[lane];
#pragma unroll
            for (int o = 1; o < 32; o <<= 1) {
                int y = __shfl_up_sync(0xffffffff, s, o);
                if (lane >= o) s += y;
            }
            wsums[lane] = s;
        }
        __syncthreads();
        int excl = x - v + (w ? wsums[w - 1] : 0) + s_carry;
        if (i < NN) rowptr[i] = excl;
        __syncthreads();
        if (t == 1023) s_carry += x + wsums[30];
        __syncthreads();
    }
    if (t == 0) rowptr[NN] = s_carry;
}

__global__ void fill_kernel(const int* __restrict__ src, const int* __restrict__ dst,
                            const int* __restrict__ rowptr, int* __restrict__ cnt,
                            int* __restrict__ col) {
    int e = blockIdx.x * blockDim.x + threadIdx.x;
    if (e >= EE) return;
    int d = dst[e];
    int pos = __ldg(rowptr + d) + atomicAdd(&cnt[d], 1);
    col[pos] = src[e];
}

// ---------- gather (bf16 in, fp32 out): agg[n] = h[n] + sum_{m} h[m] ----------
__global__ void gather_kernel(const __nv_bfloat16* __restrict__ hin0,
                              const __nv_bfloat16* __restrict__ hin1,
                              const int* __restrict__ rowptr, const int* __restrict__ col,
                              float* __restrict__ agg) {
    int enc = blockIdx.y;
    const __nv_bfloat16* hin = enc ? hin1 : hin0;
    agg += (size_t)enc * NN * DD;
    int wid = (blockIdx.x * blockDim.x + threadIdx.x) >> 5;
    if (wid >= NN) return;
    int lane = threadIdx.x & 31;
    int r0 = __ldg(rowptr + wid), r1 = __ldg(rowptr + wid + 1);
    float4 acc = bf8_to_f4(*reinterpret_cast<const uint2*>(hin + (size_t)wid * DD + lane * 4));
    for (int base = r0; base < r1; base += 32) {
        int idx = (base + lane < r1) ? __ldg(col + base + lane) : 0;
        int m = min(32, r1 - base);
        int j = 0;
        for (; j + 8 <= m; j += 8) {
            uint2 u[8];
#pragma unroll
            for (int q = 0; q < 8; q++) {
                int n = __shfl_sync(0xffffffff, idx, j + q);
                u[q] = *reinterpret_cast<const uint2*>(hin + (size_t)n * DD + lane * 4);
            }
#pragma unroll
            for (int q = 0; q < 8; q++) {
                float4 v = bf8_to_f4(u[q]);
                acc.x += v.x; acc.y += v.y; acc.z += v.z; acc.w += v.w;
            }
        }
        for (; j < m; j++) {
            int n = __shfl_sync(0xffffffff, idx, j);
            float4 v = bf8_to_f4(*reinterpret_cast<const uint2*>(hin + (size_t)n * DD + lane * 4));
            acc.x += v.x; acc.y += v.y; acc.z += v.z; acc.w += v.w;
        }
    }
    *reinterpret_cast<float4*>(agg + (size_t)wid * DD + lane * 4) = acc;
}

// ---------------- small kernels ----------------
__global__ void conv_kernel(const float* __restrict__ feat,
                            __nv_bfloat16* __restrict__ xb0,
                            __nv_bfloat16* __restrict__ xb1) {
    int idx = blockIdx.x * blockDim.x + threadIdx.x;
    if (idx >= NN * DD / 4) return;
    float4 v = reinterpret_cast<const float4*>(feat)[idx];
    uint2 u = f4_to_bf8(v);
    *reinterpret_cast<uint2*>(xb0 + (size_t)idx * 4) = u;
    *reinterpret_cast<uint2*>(xb1 + (size_t)idx * 4) = u;
}

__global__ void mask_kernel(__nv_bfloat16* __restrict__ x, const int* __restrict__ idx,
                            const float* __restrict__ tok, int nMask) {
    int i = blockIdx.x * blockDim.x + threadIdx.x;
    if (i >= nMask * DD) return;
    int m = i >> 7, c = i & 127;
    x[(size_t)idx[m] * DD + c] = __float2bfloat16_rn(tok[c]);
}

__global__ void bnrelu_pool(const float* __restrict__ Z, const float* __restrict__ stats,
                            const float* __restrict__ g0, const float* __restrict__ g1,
                            const float* __restrict__ b0, const float* __restrict__ b1,
                            const int* __restrict__ gid, __nv_bfloat16* __restrict__ hb,
                            float* __restrict__ pool, int colOff) {
    int enc = blockIdx.y;
    Z += (size_t)enc * NN * DD;
    hb += (size_t)enc * NN * DD;
    stats += (size_t)enc * ENC_ST;
    pool += (size_t)enc * BB * LL * DD;
    const float* g = enc ? g1 : g0;
    const float* b = enc ? b1 : b0;

    __shared__ __align__(16) float sab[2 * DD];
    int t = threadIdx.x;
    if (t < DD) {
        float m = stats[t] * (1.0f / NN);
        float var = stats[DD + t] * (1.0f / NN) - m * m;
        float a = g[t] * rsqrtf(var + BN_EPS);
        sab[t] = a;
        sab[DD + t] = b[t] - m * a;
    }
    __syncthreads();
    int idx = blockIdx.x * blockDim.x + t;
    if (idx >= NN * DD / 4) return;
    int r = idx >> 5;
    int c = (idx & 31) * 4;
    float4 z = *reinterpret_cast<const float4*>(Z + (size_t)idx * 4);
    float4 sa = *reinterpret_cast<const float4*>(sab + c);
    float4 sc = *reinterpret_cast<const float4*>(sab + DD + c);
    float4 v;
    v.x = fmaxf(fmaf(z.x, sa.x, sc.x), 0.f);
    v.y = fmaxf(fmaf(z.y, sa.y, sc.y), 0.f);
    v.z = fmaxf(fmaf(z.z, sa.z, sc.z), 0.f);
    v.w = fmaxf(fmaf(z.w, sa.w, sc.w), 0.f);
    *reinterpret_cast<uint2*>(hb + (size_t)idx * 4) = f4_to_bf8(v);
    red_add_v4(&pool[(size_t)gid[r] * (LL * DD) + colOff + c], v);
}

__global__ void proj_kernel(const float* __restrict__ pool, const float* __restrict__ pW1,
                            const float* __restrict__ pb1, const float* __restrict__ pW2,
                            const float* __restrict__ pb2, float* __restrict__ out) {
    __shared__ float row[LL * DD];
    __shared__ float h1[192];
    int i = blockIdx.x + blockIdx.y * BB;
    int t = threadIdx.x;
    for (int k = t; k < LL * DD; k += 192) row[k] = pool[(size_t)i * (LL * DD) + k];
    __syncthreads();
    float s = pb1[t];
    for (int k = 0; k < LL * DD; k++) s += row[k] * pW1[(size_t)k * 192 + t];
    h1[t] = fmaxf(s, 0.f);
    __syncthreads();
    if (t < 128) {
        float s2 = pb2[t];
        for (int k = 0; k < 192; k++) s2 += h1[k] * pW2[(size_t)k * 128 + t];
        out[(size_t)i * 128 + t] = s2;
    }
}

__global__ void norms_kernel(const float* __restrict__ p, float* __restrict__ nrm) {
    int row = blockIdx.x, t = threadIdx.x;
    float v = p[(size_t)row * 128 + t];
    v *= v;
    for (int o = 16; o; o >>= 1) v += __shfl_down_sync(0xffffffff, v, o);
    __shared__ float ws[4];
    if ((t & 31) == 0) ws[t >> 5] = v;
    __syncthreads();
    if (t == 0) nrm[row] = sqrtf(ws[0] + ws[1] + ws[2] + ws[3]);
}

__global__ void loss_kernel(const float* __restrict__ ch, const float* __restrict__ cm,
                            const float* __restrict__ n_ch, const float* __restrict__ n_cm,
                            float* __restrict__ out) {
    int i = blockIdx.x;
    int t = threadIdx.x;
    __shared__ float sh[128];
    __shared__ float red[256];
    __shared__ float posv;
    if (t < 128) sh[t] = ch[(size_t)i * 128 + t];
    __syncthreads();
    float d = 0.f;
    const float* rowj = cm + (size_t)t * 128;
    for (int k = 0; k < 128; k++) d += sh[k] * rowj[k];
    float s = expf(d / (n_ch[i] * n_cm[t]) * (1.0f / TEMP));
    if (t == i) posv = s;
    red[t] = s;
    __syncthreads();
    for (int o = 128; o; o >>= 1) {
        if (t < o) red[t] += red[t + o];
        __syncthreads();
    }
    if (t == 0) {
        float sum = red[0];
        float li = -logf(posv / (sum - posv));
        atomicAdd(out, li * (1.0f / BB));
    }
}

__global__ void tsplit4(const float* __restrict__ W1e, const float* __restrict__ W1c,
                        const float* __restrict__ W2e, const float* __restrict__ W2c,
                        float* __restrict__ w1h, float* __restrict__ w1l,
                        float* __restrict__ w2h, float* __restrict__ w2l) {
    int which = blockIdx.y;
    const float* W;
    float *hi, *lo;
    int K, N;
    if (which == 0)      { W = W1e; hi = w1h;         lo = w1l;         K = DD; N = HH; }
    else if (which == 1) { W = W1c; hi = w1h + ENC_W; lo = w1l + ENC_W; K = DD; N = HH; }
    else if (which == 2) { W = W2e; hi = w2h;         lo = w2l;         K = HH; N = DD; }
    else                 { W = W2c; hi = w2h + ENC_W; lo = w2l + ENC_W; K = HH; N = DD; }
    int i = blockIdx.x * blockDim.x + threadIdx.x;
    if (i >= ENC_W) return;
    int l = i / (K * N), rem = i % (K * N);
    int k = rem / N, n = rem % N;
    float v = W[i];
    float h = tf32_round(v);
    size_t o = (size_t)l * K * N + (size_t)n * K + k;
    hi[o] = h;
    lo[o] = v - h;
}

// ---------------- 2xTF32 mma.sync GEMM (both encoders via blockIdx.z) ---------
// MODE 0: A fp32 (agg), C bf16 (z1).  MODE 1: A bf16 (z1) + fused BN+ReLU, C fp32 (z2).
// Padding rows (row >= M) contribute ZERO to stats in both modes.
#define PAD 36
#define GEMM_SMEM ((3 * 128 * PAD + 2 * 256) * 4)   // 57344 B

template <int MODE, int NT, int KT>
__global__ __launch_bounds__(256, 2)
void gemm_mma(const void* __restrict__ Av, const float* __restrict__ Bh,
              const float* __restrict__ Bl, void* __restrict__ Cv,
              float* __restrict__ stats_out, const float* __restrict__ stats_in,
              const float* __restrict__ g0, const float* __restrict__ g1,
              const float* __restrict__ b0, const float* __restrict__ b1, int M) {
    const int enc = blockIdx.z;
    Bh += (size_t)enc * ENC_W;
    Bl += (size_t)enc * ENC_W;
    stats_out += (size_t)enc * ENC_ST;
    const float* g = enc ? g1 : g0;
    const float* b = enc ? b1 : b0;

    extern __shared__ float sm[];
    float* As  = sm;
    float* Bhs = As + 128 * PAD;
    float* Bls = Bhs + 128 * PAD;
    float* sab = Bls + 128 * PAD;
    __shared__ float ssum[128], ssq[128];

    const int tid = threadIdx.x;
    const int lane = tid & 31, w = tid >> 5;
    const int mw = w >> 2, nw = w & 3;
    const int bm = blockIdx.x * 128, bn = blockIdx.y * 128;

    if (MODE == 1) {
        const float* si = stats_in + (size_t)enc * ENC_ST;
        for (int i = tid; i < KT; i += 256) {
            float m = si[i] * (1.0f / NN);
            float var = si[KT + i] * (1.0f / NN) - m * m;
            float a = g[i] * rsqrtf(var + BN_EPS);
            sab[i] = a;
            sab[KT + i] = b[i] - m * a;
        }
        __syncthreads();
    }

    float acc[4][4][4];
#pragma unroll
    for (int mi = 0; mi < 4; mi++)
#pragma unroll
        for (int ni = 0; ni < 4; ni++)
#pragma unroll
            for (int r = 0; r < 4; r++) acc[mi][ni][r] = 0.f;

    const int lrow = tid >> 1;
    const int lcol0 = (tid & 1) * 16;
    const bool rok = (bm + lrow) < M;
    const float* ArowF = (MODE == 0)
        ? (const float*)Av + (size_t)enc * NN * KT + (size_t)(bm + lrow) * KT : nullptr;
    const __nv_bfloat16* ArowB = (MODE == 1)
        ? (const __nv_bfloat16*)Av + (size_t)enc * NN * KT + (size_t)(bm + lrow) * KT : nullptr;
    const float* Bhrow = Bh + (size_t)(bn + lrow) * KT;
    const float* Blrow = Bl + (size_t)(bn + lrow) * KT;

    const int frow = lane >> 2;
    const int fcol = lane & 3;

    for (int k0 = 0; k0 < KT; k0 += 32) {
        // ---- stage A ----
        if (MODE == 0) {
#pragma unroll
            for (int i = 0; i < 4; i++) {
                int col = lcol0 + i * 4;
                float4 v = make_float4(0.f, 0.f, 0.f, 0.f);
                if (rok) v = *reinterpret_cast<const float4*>(ArowF + k0 + col);
                As[lrow * PAD + col + 0] = tf32_round(v.x);
                As[lrow * PAD + col + 1] = tf32_round(v.y);
                As[lrow * PAD + col + 2] = tf32_round(v.z);
                As[lrow * PAD + col + 3] = tf32_round(v.w);
            }
        } else {
#pragma unroll
            for (int half = 0; half < 2; half++) {
                uint4 u = make_uint4(0, 0, 0, 0);
                if (rok) u = *reinterpret_cast<const uint4*>(ArowB + k0 + lcol0 + half * 8);
                uint32_t uu[4] = {u.x, u.y, u.z, u.w};
#pragma unroll
                for (int j = 0; j < 4; j++) {
                    __nv_bfloat162 bb = *reinterpret_cast<__nv_bfloat162*>(&uu[j]);
                    float2 f = __bfloat1622float2(bb);
                    int col = lcol0 + half * 8 + j * 2;
                    // OOB rows must stay exactly zero (they feed the fused stats)
                    float a0 = rok ? fmaxf(fmaf(f.x, sab[col], sab[KT + col]), 0.f) : 0.f;
                    float a1 = rok ? fmaxf(fmaf(f.y, sab[col + 1], sab[KT + col + 1]), 0.f) : 0.f;
                    As[lrow * PAD + col] = tf32_round(a0);
                    As[lrow * PAD + col + 1] = tf32_round(a1);
                }
            }
        }
        // ---- stage B ----
#pragma unroll
        for (int i = 0; i < 4; i++) {
            int col = lcol0 + i * 4;
            float4 vh = *reinterpret_cast<const float4*>(Bhrow + k0 + col);
            float4 vl = *reinterpret_cast<const float4*>(Blrow + k0 + col);
            *reinterpret_cast<float4*>(Bhs + lrow * PAD + col) = vh;
            *reinterpret_cast<float4*>(Bls + lrow * PAD + col) = vl;
        }
        __syncthreads();

#pragma unroll
        for (int kk = 0; kk < 4; kk++) {
            const int k = kk * 8;
            uint32_t af[4][4];
#pragma unroll
            for (int mi = 0; mi < 4; mi++) {
                int r0 = mw * 64 + mi * 16 + frow;
                int c0 = k + fcol;
                af[mi][0] = __float_as_uint(As[r0 * PAD + c0]);
                af[mi][1] = __float_as_uint(As[(r0 + 8) * PAD + c0]);
                af[mi][2] = __float_as_uint(As[r0 * PAD + c0 + 4]);
                af[mi][3] = __float_as_uint(As[(r0 + 8) * PAD + c0 + 4]);
            }
            uint32_t bfh[4][2], bfl[4][2];
#pragma unroll
            for (int ni = 0; ni < 4; ni++) {
                int n0 = nw * 32 + ni * 8 + frow;
                int kb = k + fcol;
                bfh[ni][0] = __float_as_uint(Bhs[n0 * PAD + kb]);
                bfh[ni][1] = __float_as_uint(Bhs[n0 * PAD + kb + 4]);
                bfl[ni][0] = __float_as_uint(Bls[n0 * PAD + kb]);
                bfl[ni][1] = __float_as_uint(Bls[n0 * PAD + kb + 4]);
            }
#pragma unroll
            for (int mi = 0; mi < 4; mi++)
#pragma unroll
                for (int ni = 0; ni < 4; ni++) {
                    mma_tf32(acc[mi][ni], af[mi], bfh[ni]);
                    mma_tf32(acc[mi][ni], af[mi], bfl[ni]);
                }
        }
        __syncthreads();
    }

    // ---- epilogue: C store + fused column stats ----
    if (tid < 128) { ssum[tid] = 0.f; ssq[tid] = 0.f; }
    __syncthreads();

#pragma unroll
    for (int mi = 0; mi < 4; mi++) {
#pragma unroll
        for (int ni = 0; ni < 4; ni++) {
            int row = bm + mw * 64 + mi * 16 + frow;
            int coll = nw * 32 + ni * 8 + 2 * fcol;
            float* a = acc[mi][ni];
            if (MODE == 0) {
                __nv_bfloat16* Cb = (__nv_bfloat16*)Cv + (size_t)enc * NN * NT;
                if (row < M)
                    *reinterpret_cast<__nv_bfloat162*>(Cb + (size_t)row * NT + bn + coll) =
                        __floats2bfloat162_rn(a[0], a[1]);
                if (row + 8 < M)
                    *reinterpret_cast<__nv_bfloat162*>(Cb + (size_t)(row + 8) * NT + bn + coll) =
                        __floats2bfloat162_rn(a[2], a[3]);
            } else {
                float* Cf = (float*)Cv + (size_t)enc * NN * NT;
                if (row < M)
                    *reinterpret_cast<float2*>(Cf + (size_t)row * NT + bn + coll) =
                        make_float2(a[0], a[1]);
                if (row + 8 < M)
                    *reinterpret_cast<float2*>(Cf + (size_t)(row + 8) * NT + bn + coll) =
                        make_float2(a[2], a[3]);
            }
        }
    }

#pragma unroll
    for (int ni = 0; ni < 4; ni++) {
        float s0 = 0.f, s1 = 0.f, q0 = 0.f, q1 = 0.f;
#pragma unroll
        for (int mi = 0; mi < 4; mi++) {
            float* a = acc[mi][ni];
            s0 += a[0] + a[2];
            s1 += a[1] + a[3];
            q0 += a[0] * a[0] + a[2] * a[2];
            q1 += a[1] * a[1] + a[3] * a[3];
        }
#pragma unroll
        for (int off = 4; off < 32; off <<= 1) {
            s0 += __shfl_xor_sync(0xffffffff, s0, off);
            s1 += __shfl_xor_sync(0xffffffff, s1, off);
            q0 += __shfl_xor_sync(0xffffffff, q0, off);
            q1 += __shfl_xor_sync(0xffffffff, q1, off);
        }
        if (lane < 4) {
            int coll = nw * 32 + ni * 8 + 2 * fcol;
            atomicAdd(&ssum[coll], s0);
            atomicAdd(&ssum[coll + 1], s1);
            atomicAdd(&ssq[coll], q0);
            atomicAdd(&ssq[coll + 1], q1);
        }
    }
    __syncthreads();
    if (tid < 128) {
        atomicAdd(&stats_out[bn + tid], ssum[tid]);
        atomicAdd(&stats_out[NT + bn + tid], ssq[tid]);
    }
}

// ---------------- host orchestration ----------------

extern "C" void kernel_launch(void* const* d_in, const int* in_sizes, int n_in,
                              void* d_out, int out_size) {
    const float* feat       = (const float*)d_in[0];
    const int*   src        = (const int*)d_in[1];
    const int*   dst        = (const int*)d_in[2];
    const int*   graph_ids  = (const int*)d_in[3];
    const int*   mask_nodes = (const int*)d_in[4];
    const float* mask_token = (const float*)d_in[5];
    const float* enc_W1 = (const float*)d_in[6];
    const float* enc_g1 = (const float*)d_in[7];
    const float* enc_b1 = (const float*)d_in[8];
    const float* enc_W2 = (const float*)d_in[9];
    const float* enc_g2 = (const float*)d_in[10];
    const float* enc_b2 = (const float*)d_in[11];
    const float* con_W1 = (const float*)d_in[12];
    const float* con_g1 = (const float*)d_in[13];
    const float* con_b1 = (const float*)d_in[14];
    const float* con_W2 = (const float*)d_in[15];
    const float* con_g2 = (const float*)d_in[16];
    const float* con_b2 = (const float*)d_in[17];
    const float* pW1 = (const float*)d_in[18];
    const float* pb1 = (const float*)d_in[19];
    const float* pW2 = (const float*)d_in[20];
    const float* pb2 = (const float*)d_in[21];
    int nMask = in_sizes[4];

    float *pool, *statsArena, *p2, *norms, *agg, *z2;
    __nv_bfloat16 *xb, *hb, *z1b;
    float *w1h, *w1l, *w2h, *w2l;
    int *rowptr, *cnt, *colidx;
    cudaGetSymbolAddress((void**)&xb, g_xb);
    cudaGetSymbolAddress((void**)&hb, g_hb);
    cudaGetSymbolAddress((void**)&z1b, g_z1b);
    cudaGetSymbolAddress((void**)&agg, g_agg);
    cudaGetSymbolAddress((void**)&z2, g_z2);
    cudaGetSymbolAddress((void**)&statsArena, g_statsArena);
    cudaGetSymbolAddress((void**)&pool, g_pool);
    cudaGetSymbolAddress((void**)&p2, g_p2);
    cudaGetSymbolAddress((void**)&norms, g_norms);
    cudaGetSymbolAddress((void**)&w1h, g_W1T_hi);
    cudaGetSymbolAddress((void**)&w1l, g_W1T_lo);
    cudaGetSymbolAddress((void**)&w2h, g_W2T_hi);
    cudaGetSymbolAddress((void**)&w2l, g_W2T_lo);
    cudaGetSymbolAddress((void**)&rowptr, g_rowptr);
    cudaGetSymbolAddress((void**)&cnt, g_cnt);
    cudaGetSymbolAddress((void**)&colidx, g_col);

    cudaFuncSetAttribute(gemm_mma<0, HH, DD>, cudaFuncAttributeMaxDynamicSharedMemorySize, GEMM_SMEM);
    cudaFuncSetAttribute(gemm_mma<1, DD, HH>, cudaFuncAttributeMaxDynamicSharedMemorySize, GEMM_SMEM);

    // ---- prep ----
    cudaMemsetAsync(cnt, 0, NN * sizeof(int));
    count_kernel<<<(EE + 255) / 256, 256>>>(dst, cnt);
    scan_kernel<<<1, 1024>>>(cnt, rowptr);
    cudaMemsetAsync(cnt, 0, NN * sizeof(int));
    fill_kernel<<<(EE + 255) / 256, 256>>>(src, dst, rowptr, cnt, colidx);

    tsplit4<<<dim3((ENC_W + 255) / 256, 4), 256>>>(enc_W1, con_W1, enc_W2, con_W2,
                                                   w1h, w1l, w2h, w2l);

    conv_kernel<<<(NN * DD / 4 + 255) / 256, 256>>>(feat, xb, xb + (size_t)NN * DD);
    mask_kernel<<<(nMask * DD + 255) / 256, 256>>>(xb, mask_nodes, mask_token, nMask);

    cudaMemsetAsync(pool, 0, 2 * BB * LL * DD * sizeof(float));
    cudaMemsetAsync(statsArena, 0, 2 * LL * 2 * 512 * sizeof(float));
    cudaMemsetAsync(d_out, 0, sizeof(float));

    // ---- both encoders, batched per stage ----
    const int GB = (NN + 127) / 128;   // 391
    for (int l = 0; l < LL; l++) {
        const __nv_bfloat16* in0 = l == 0 ? xb : hb;
        const __nv_bfloat16* in1 = (l == 0 ? xb : hb) + (size_t)NN * DD;
        gather_kernel<<<dim3((NN * 32 + 255) / 256, 2), 256>>>(in0, in1, rowptr, colidx, agg);

        float* st1 = statsArena + l * 1024;
        float* st2 = st1 + 512;
        gemm_mma<0, HH, DD><<<dim3(GB, HH / 128, 2), 256, GEMM_SMEM>>>(
            agg, w1h + (size_t)l * HH * DD, w1l + (size_t)l * HH * DD,
            z1b, st1, nullptr, nullptr, nullptr, nullptr, nullptr, NN);
        gemm_mma<1, DD, HH><<<dim3(GB, 1, 2), 256, GEMM_SMEM>>>(
            z1b, w2h + (size_t)l * DD * HH, w2l + (size_t)l * DD * HH,
            z2, st2, st1,
            enc_g1 + l * HH, con_g1 + l * HH, enc_b1 + l * HH, con_b1 + l * HH, NN);

        bnrelu_pool<<<dim3((NN * DD / 4 + 255) / 256, 2), 256>>>(
            z2, st2, enc_g2 + l * DD, con_g2 + l * DD,
            enc_b2 + l * DD, con_b2 + l * DD, graph_ids, hb, pool, l * DD);
    }

    // ---- tail ----
    proj_kernel<<<dim3(BB, 2), 192>>>(pool, pW1, pb1, pW2, pb2, p2);
    norms_kernel<<<2 * BB, 128>>>(p2, norms);
    loss_kernel<<<BB, 256>>>(p2 + BB * 128, p2, norms + BB, norms, (float*)d_out);
}

// round 16
// speedup vs baseline: 1.0519x; 1.0519x over previous
#include <cuda_runtime.h>
#include <cuda_bf16.h>
#include <math.h>
#include <stdint.h>

#define NN 50000
#define EE 800000
#define BB 256
#define DD 128
#define HH 256
#define LL 3
#define TEMP 0.2f
#define BN_EPS 1e-5f

// ---------------- scratch (device globals) ----------------
__device__ __align__(16) __nv_bfloat16 g_xb[2][(size_t)NN * DD];
__device__ __align__(16) __nv_bfloat16 g_hb[2][(size_t)NN * DD];
__device__ __align__(16) __nv_bfloat16 g_z1b[2][(size_t)NN * HH];
__device__ __align__(16) __nv_bfloat16 g_aggb[2][(size_t)NN * DD];
__device__ __align__(16) float g_z2[2][(size_t)NN * DD];
__device__ __align__(16) float g_statsArena[2 * LL * 2 * 512];
__device__ __align__(16) float g_pool[2 * BB * LL * DD];
__device__ __align__(16) float g_p2[2 * BB * 128];
__device__ __align__(16) float g_W1T_hi[2 * LL * HH * DD];
__device__ __align__(16) float g_W1T_lo[2 * LL * HH * DD];
__device__ __align__(16) float g_W2T_hi[2 * LL * DD * HH];
__device__ __align__(16) float g_W2T_lo[2 * LL * DD * HH];
__device__ int g_rowptr[NN + 1];
__device__ int g_cnt[NN];
__device__ int g_col[EE];

#define ENC_W (LL * DD * HH)
#define ENC_ST (LL * 1024)

// ---------------- helpers ----------------
__device__ __forceinline__ float tf32_round(float x) {
    uint32_t u;
    asm("cvt.rna.tf32.f32 %0, %1;" : "=r"(u) : "f"(x));
    return __uint_as_float(u);
}
__device__ __forceinline__ void red_add_v4(float* p, float4 v) {
    asm volatile("red.global.add.v4.f32 [%0], {%1,%2,%3,%4};"
                 :: "l"(p), "f"(v.x), "f"(v.y), "f"(v.z), "f"(v.w) : "memory");
}
__device__ __forceinline__ void mma_tf32(float* c, const uint32_t* a, const uint32_t* b) {
    asm volatile(
        "mma.sync.aligned.m16n8k8.row.col.f32.tf32.tf32.f32 "
        "{%0,%1,%2,%3}, {%4,%5,%6,%7}, {%8,%9}, {%0,%1,%2,%3};"
        : "+f"(c[0]), "+f"(c[1]), "+f"(c[2]), "+f"(c[3])
        : "r"(a[0]), "r"(a[1]), "r"(a[2]), "r"(a[3]), "r"(b[0]), "r"(b[1]));
}
__device__ __forceinline__ float4 bf8_to_f4(uint2 u) {
    __nv_bfloat162 b0 = *reinterpret_cast<__nv_bfloat162*>(&u.x);
    __nv_bfloat162 b1 = *reinterpret_cast<__nv_bfloat162*>(&u.y);
    float2 f0 = __bfloat1622float2(b0);
    float2 f1 = __bfloat1622float2(b1);
    return make_float4(f0.x, f0.y, f1.x, f1.y);
}
__device__ __forceinline__ uint2 f4_to_bf8(float4 v) {
    __nv_bfloat162 p0 = __floats2bfloat162_rn(v.x, v.y);
    __nv_bfloat162 p1 = __floats2bfloat162_rn(v.z, v.w);
    uint2 u;
    u.x = *reinterpret_cast<uint32_t*>(&p0);
    u.y = *reinterpret_cast<uint32_t*>(&p1);
    return u;
}

// ---------------- CSR build ----------------
__global__ void count_kernel(const int* __restrict__ dst, int* __restrict__ cnt) {
    int e = blockIdx.x * blockDim.x + threadIdx.x;
    if (e < EE) atomicAdd(&cnt[dst[e]], 1);
}

__global__ void scan_kernel(const int* __restrict__ cnt, int* __restrict__ rowptr) {
    __shared__ int wsums[32];
    __shared__ int s_carry;
    int t = threadIdx.x, lane = t & 31, w = t >> 5;
    if (t == 0) s_carry = 0;
    __syncthreads();
    for (int base = 0; base < NN; base += 1024) {
        int i = base + t;
        int v = (i < NN) ? cnt[i] : 0;
        int x = v;
#pragma unroll
        for (int o = 1; o < 32; o <<= 1) {
            int y = __shfl_up_sync(0xffffffff, x, o);
            if (lane >= o) x += y;
        }
        if (lane == 31) wsums[w] = x;
        __syncthreads();
        if (w == 0) {
            int s = wsums[lane];
#pragma unroll
            for (int o = 1; o < 32; o <<= 1) {
                int y = __shfl_up_sync(0xffffffff, s, o);
                if (lane >= o) s += y;
            }
            wsums[lane] = s;
        }
        __syncthreads();
        int excl = x - v + (w ? wsums[w - 1] : 0) + s_carry;
        if (i < NN) rowptr[i] = excl;
        __syncthreads();
        if (t == 1023) s_carry += x + wsums[30];
        __syncthreads();
    }
    if (t == 0) rowptr[NN] = s_carry;
}

__global__ void fill_kernel(const int* __restrict__ src, const int* __restrict__ dst,
                            const int* __restrict__ rowptr, int* __restrict__ cnt,
                            int* __restrict__ col) {
    int e = blockIdx.x * blockDim.x + threadIdx.x;
    if (e >= EE) return;
    int d = dst[e];
    int pos = __ldg(rowptr + d) + atomicAdd(&cnt[d], 1);
    col[pos] = src[e];
}

// ---- gather (bf16 in, bf16 out): agg[n] = h[n] + sum_{m} h[m] (fp32 acc) ----
__global__ void gather_kernel(const __nv_bfloat16* __restrict__ hin0,
                              const __nv_bfloat16* __restrict__ hin1,
                              const int* __restrict__ rowptr, const int* __restrict__ col,
                              __nv_bfloat16* __restrict__ aggb) {
    int enc = blockIdx.y;
    const __nv_bfloat16* hin = enc ? hin1 : hin0;
    aggb += (size_t)enc * NN * DD;
    int wid = (blockIdx.x * blockDim.x + threadIdx.x) >> 5;
    if (wid >= NN) return;
    int lane = threadIdx.x & 31;
    int r0 = __ldg(rowptr + wid), r1 = __ldg(rowptr + wid + 1);
    float4 acc = bf8_to_f4(*reinterpret_cast<const uint2*>(hin + (size_t)wid * DD + lane * 4));
    for (int base = r0; base < r1; base += 32) {
        int idx = (base + lane < r1) ? __ldg(col + base + lane) : 0;
        int m = min(32, r1 - base);
        int j = 0;
        for (; j + 4 <= m; j += 4) {
            int n0 = __shfl_sync(0xffffffff, idx, j);
            int n1 = __shfl_sync(0xffffffff, idx, j + 1);
            int n2 = __shfl_sync(0xffffffff, idx, j + 2);
            int n3 = __shfl_sync(0xffffffff, idx, j + 3);
            uint2 u0 = *reinterpret_cast<const uint2*>(hin + (size_t)n0 * DD + lane * 4);
            uint2 u1 = *reinterpret_cast<const uint2*>(hin + (size_t)n1 * DD + lane * 4);
            uint2 u2 = *reinterpret_cast<const uint2*>(hin + (size_t)n2 * DD + lane * 4);
            uint2 u3 = *reinterpret_cast<const uint2*>(hin + (size_t)n3 * DD + lane * 4);
            float4 v0 = bf8_to_f4(u0);
            float4 v1 = bf8_to_f4(u1);
            float4 v2 = bf8_to_f4(u2);
            float4 v3 = bf8_to_f4(u3);
            acc.x += v0.x + v1.x + v2.x + v3.x;
            acc.y += v0.y + v1.y + v2.y + v3.y;
            acc.z += v0.z + v1.z + v2.z + v3.z;
            acc.w += v0.w + v1.w + v2.w + v3.w;
        }
        for (; j < m; j++) {
            int n = __shfl_sync(0xffffffff, idx, j);
            float4 v = bf8_to_f4(*reinterpret_cast<const uint2*>(hin + (size_t)n * DD + lane * 4));
            acc.x += v.x; acc.y += v.y; acc.z += v.z; acc.w += v.w;
        }
    }
    *reinterpret_cast<uint2*>(aggb + (size_t)wid * DD + lane * 4) = f4_to_bf8(acc);
}

// ---------------- small kernels ----------------
__global__ void conv_kernel(const float* __restrict__ feat,
                            __nv_bfloat16* __restrict__ xb0,
                            __nv_bfloat16* __restrict__ xb1) {
    int idx = blockIdx.x * blockDim.x + threadIdx.x;
    if (idx >= NN * DD / 4) return;
    float4 v = reinterpret_cast<const float4*>(feat)[idx];
    uint2 u = f4_to_bf8(v);
    *reinterpret_cast<uint2*>(xb0 + (size_t)idx * 4) = u;
    *reinterpret_cast<uint2*>(xb1 + (size_t)idx * 4) = u;
}

__global__ void mask_kernel(__nv_bfloat16* __restrict__ x, const int* __restrict__ idx,
                            const float* __restrict__ tok, int nMask) {
    int i = blockIdx.x * blockDim.x + threadIdx.x;
    if (i >= nMask * DD) return;
    int m = i >> 7, c = i & 127;
    x[(size_t)idx[m] * DD + c] = __float2bfloat16_rn(tok[c]);
}

__global__ void bnrelu_pool(const float* __restrict__ Z, const float* __restrict__ stats,
                            const float* __restrict__ g0, const float* __restrict__ g1,
                            const float* __restrict__ b0, const float* __restrict__ b1,
                            const int* __restrict__ gid, __nv_bfloat16* __restrict__ hb,
                            float* __restrict__ pool, int colOff) {
    int enc = blockIdx.y;
    Z += (size_t)enc * NN * DD;
    hb += (size_t)enc * NN * DD;
    stats += (size_t)enc * ENC_ST;
    pool += (size_t)enc * BB * LL * DD;
    const float* g = enc ? g1 : g0;
    const float* b = enc ? b1 : b0;

    __shared__ __align__(16) float sab[2 * DD];
    int t = threadIdx.x;
    if (t < DD) {
        float m = stats[t] * (1.0f / NN);
        float var = stats[DD + t] * (1.0f / NN) - m * m;
        float a = g[t] * rsqrtf(var + BN_EPS);
        sab[t] = a;
        sab[DD + t] = b[t] - m * a;
    }
    __syncthreads();
    int idx = blockIdx.x * blockDim.x + t;
    if (idx >= NN * DD / 4) return;
    int r = idx >> 5;
    int c = (idx & 31) * 4;
    float4 z = *reinterpret_cast<const float4*>(Z + (size_t)idx * 4);
    float4 sa = *reinterpret_cast<const float4*>(sab + c);
    float4 sc = *reinterpret_cast<const float4*>(sab + DD + c);
    float4 v;
    v.x = fmaxf(fmaf(z.x, sa.x, sc.x), 0.f);
    v.y = fmaxf(fmaf(z.y, sa.y, sc.y), 0.f);
    v.z = fmaxf(fmaf(z.z, sa.z, sc.z), 0.f);
    v.w = fmaxf(fmaf(z.w, sa.w, sc.w), 0.f);
    *reinterpret_cast<uint2*>(hb + (size_t)idx * 4) = f4_to_bf8(v);
    red_add_v4(&pool[(size_t)gid[r] * (LL * DD) + colOff + c], v);
}

__global__ void proj_kernel(const float* __restrict__ pool, const float* __restrict__ pW1,
                            const float* __restrict__ pb1, const float* __restrict__ pW2,
                            const float* __restrict__ pb2, float* __restrict__ out) {
    __shared__ float row[LL * DD];
    __shared__ float h1[192];
    int i = blockIdx.x + blockIdx.y * BB;
    int t = threadIdx.x;
    for (int k = t; k < LL * DD; k += 192) row[k] = pool[(size_t)i * (LL * DD) + k];
    __syncthreads();
    float s = pb1[t];
    for (int k = 0; k < LL * DD; k++) s += row[k] * pW1[(size_t)k * 192 + t];
    h1[t] = fmaxf(s, 0.f);
    __syncthreads();
    if (t < 128) {
        float s2 = pb2[t];
        for (int k = 0; k < 192; k++) s2 += h1[k] * pW2[(size_t)k * 128 + t];
        out[(size_t)i * 128 + t] = s2;
    }
}

// loss with norms computed inline (norms_kernel folded in)
__global__ void loss_kernel(const float* __restrict__ ch, const float* __restrict__ cm,
                            float* __restrict__ out) {
    int i = blockIdx.x;
    int t = threadIdx.x;
    __shared__ float sh[128];
    __shared__ float red[256];
    __shared__ float posv;
    if (t < 128) sh[t] = ch[(size_t)i * 128 + t];
    __syncthreads();
    const float* rowj = cm + (size_t)t * 128;
    float d = 0.f, q = 0.f, p = 0.f;
    for (int k = 0; k < 128; k++) {
        float a = sh[k], bq = rowj[k];
        d = fmaf(a, bq, d);
        q = fmaf(bq, bq, q);
        p = fmaf(a, a, p);
    }
    float s = expf(d / (sqrtf(p) * sqrtf(q)) * (1.0f / TEMP));
    if (t == i) posv = s;
    red[t] = s;
    __syncthreads();
    for (int o = 128; o; o >>= 1) {
        if (t < o) red[t] += red[t + o];
        __syncthreads();
    }
    if (t == 0) {
        float sum = red[0];
        float li = -logf(posv / (sum - posv));
        atomicAdd(out, li * (1.0f / BB));
    }
}

__global__ void tsplit4(const float* __restrict__ W1e, const float* __restrict__ W1c,
                        const float* __restrict__ W2e, const float* __restrict__ W2c,
                        float* __restrict__ w1h, float* __restrict__ w1l,
                        float* __restrict__ w2h, float* __restrict__ w2l) {
    int which = blockIdx.y;
    const float* W;
    float *hi, *lo;
    int K, N;
    if (which == 0)      { W = W1e; hi = w1h;         lo = w1l;         K = DD; N = HH; }
    else if (which == 1) { W = W1c; hi = w1h + ENC_W; lo = w1l + ENC_W; K = DD; N = HH; }
    else if (which == 2) { W = W2e; hi = w2h;         lo = w2l;         K = HH; N = DD; }
    else                 { W = W2c; hi = w2h + ENC_W; lo = w2l + ENC_W; K = HH; N = DD; }
    int i = blockIdx.x * blockDim.x + threadIdx.x;
    if (i >= ENC_W) return;
    int l = i / (K * N), rem = i % (K * N);
    int k = rem / N, n = rem % N;
    float v = W[i];
    float h = tf32_round(v);
    size_t o = (size_t)l * K * N + (size_t)n * K + k;
    hi[o] = h;
    lo[o] = v - h;
}

// ---------------- 2xTF32 mma.sync GEMM (both encoders via blockIdx.z) ---------
// A is bf16 in BOTH modes. MODE 0: plain A (agg), C bf16 (z1).
// MODE 1: A=z1 with fused BN+ReLU, C fp32 (z2). OOB rows contribute 0 to stats.
#define PAD 36
#define GEMM_SMEM ((3 * 128 * PAD + 2 * 256) * 4)   // 57344 B

template <int MODE, int NT, int KT>
__global__ __launch_bounds__(256, 2)
void gemm_mma(const __nv_bfloat16* __restrict__ Ab, const float* __restrict__ Bh,
              const float* __restrict__ Bl, void* __restrict__ Cv,
              float* __restrict__ stats_out, const float* __restrict__ stats_in,
              const float* __restrict__ g0, const float* __restrict__ g1,
              const float* __restrict__ b0, const float* __restrict__ b1, int M) {
    const int enc = blockIdx.z;
    Bh += (size_t)enc * ENC_W;
    Bl += (size_t)enc * ENC_W;
    stats_out += (size_t)enc * ENC_ST;
    const float* g = enc ? g1 : g0;
    const float* b = enc ? b1 : b0;

    extern __shared__ float sm[];
    float* As  = sm;
    float* Bhs = As + 128 * PAD;
    float* Bls = Bhs + 128 * PAD;
    float* sab = Bls + 128 * PAD;
    __shared__ float ssum[128], ssq[128];

    const int tid = threadIdx.x;
    const int lane = tid & 31, w = tid >> 5;
    const int mw = w >> 2, nw = w & 3;
    const int bm = blockIdx.x * 128, bn = blockIdx.y * 128;

    if (MODE == 1) {
        const float* si = stats_in + (size_t)enc * ENC_ST;
        for (int i = tid; i < KT; i += 256) {
            float m = si[i] * (1.0f / NN);
            float var = si[KT + i] * (1.0f / NN) - m * m;
            float a = g[i] * rsqrtf(var + BN_EPS);
            sab[i] = a;
            sab[KT + i] = b[i] - m * a;
        }
        __syncthreads();
    }

    float acc[4][4][4];
#pragma unroll
    for (int mi = 0; mi < 4; mi++)
#pragma unroll
        for (int ni = 0; ni < 4; ni++)
#pragma unroll
            for (int r = 0; r < 4; r++) acc[mi][ni][r] = 0.f;

    const int lrow = tid >> 1;
    const int lcol0 = (tid & 1) * 16;
    const bool rok = (bm + lrow) < M;
    const __nv_bfloat16* ArowB = Ab + (size_t)enc * NN * KT + (size_t)(bm + lrow) * KT;
    const float* Bhrow = Bh + (size_t)(bn + lrow) * KT;
    const float* Blrow = Bl + (size_t)(bn + lrow) * KT;

    const int frow = lane >> 2;
    const int fcol = lane & 3;

    for (int k0 = 0; k0 < KT; k0 += 32) {
        // ---- stage A (bf16 -> tf32; MODE1 applies BN+ReLU; OOB rows -> 0) ----
#pragma unroll
        for (int half = 0; half < 2; half++) {
            uint4 u = make_uint4(0, 0, 0, 0);
            if (rok) u = *reinterpret_cast<const uint4*>(ArowB + k0 + lcol0 + half * 8);
            uint32_t uu[4] = {u.x, u.y, u.z, u.w};
#pragma unroll
            for (int j = 0; j < 4; j++) {
                __nv_bfloat162 bb = *reinterpret_cast<__nv_bfloat162*>(&uu[j]);
                float2 f = __bfloat1622float2(bb);
                int col = lcol0 + half * 8 + j * 2;
                float a0, a1;
                if (MODE == 1) {
                    a0 = rok ? fmaxf(fmaf(f.x, sab[col], sab[KT + col]), 0.f) : 0.f;
                    a1 = rok ? fmaxf(fmaf(f.y, sab[col + 1], sab[KT + col + 1]), 0.f) : 0.f;
                } else {
                    a0 = f.x;
                    a1 = f.y;
                }
                As[lrow * PAD + col] = tf32_round(a0);
                As[lrow * PAD + col + 1] = tf32_round(a1);
            }
        }
        // ---- stage B ----
#pragma unroll
        for (int i = 0; i < 4; i++) {
            int col = lcol0 + i * 4;
            float4 vh = *reinterpret_cast<const float4*>(Bhrow + k0 + col);
            float4 vl = *reinterpret_cast<const float4*>(Blrow + k0 + col);
            *reinterpret_cast<float4*>(Bhs + lrow * PAD + col) = vh;
            *reinterpret_cast<float4*>(Bls + lrow * PAD + col) = vl;
        }
        __syncthreads();

#pragma unroll
        for (int kk = 0; kk < 4; kk++) {
            const int k = kk * 8;
            uint32_t af[4][4];
#pragma unroll
            for (int mi = 0; mi < 4; mi++) {
                int r0 = mw * 64 + mi * 16 + frow;
                int c0 = k + fcol;
                af[mi][0] = __float_as_uint(As[r0 * PAD + c0]);
                af[mi][1] = __float_as_uint(As[(r0 + 8) * PAD + c0]);
                af[mi][2] = __float_as_uint(As[r0 * PAD + c0 + 4]);
                af[mi][3] = __float_as_uint(As[(r0 + 8) * PAD + c0 + 4]);
            }
            uint32_t bfh[4][2], bfl[4][2];
#pragma unroll
            for (int ni = 0; ni < 4; ni++) {
                int n0 = nw * 32 + ni * 8 + frow;
                int kb = k + fcol;
                bfh[ni][0] = __float_as_uint(Bhs[n0 * PAD + kb]);
                bfh[ni][1] = __float_as_uint(Bhs[n0 * PAD + kb + 4]);
                bfl[ni][0] = __float_as_uint(Bls[n0 * PAD + kb]);
                bfl[ni][1] = __float_as_uint(Bls[n0 * PAD + kb + 4]);
            }
#pragma unroll
            for (int mi = 0; mi < 4; mi++)
#pragma unroll
                for (int ni = 0; ni < 4; ni++) {
                    mma_tf32(acc[mi][ni], af[mi], bfh[ni]);
                    mma_tf32(acc[mi][ni], af[mi], bfl[ni]);
                }
        }
        __syncthreads();
    }

    // ---- epilogue: C store + fused column stats ----
    if (tid < 128) { ssum[tid] = 0.f; ssq[tid] = 0.f; }
    __syncthreads();

#pragma unroll
    for (int mi = 0; mi < 4; mi++) {
#pragma unroll
        for (int ni = 0; ni < 4; ni++) {
            int row = bm + mw * 64 + mi * 16 + frow;
            int coll = nw * 32 + ni * 8 + 2 * fcol;
            float* a = acc[mi][ni];
            if (MODE == 0) {
                __nv_bfloat16* Cb = (__nv_bfloat16*)Cv + (size_t)enc * NN * NT;
                if (row < M)
                    *reinterpret_cast<__nv_bfloat162*>(Cb + (size_t)row * NT + bn + coll) =
                        __floats2bfloat162_rn(a[0], a[1]);
                if (row + 8 < M)
                    *reinterpret_cast<__nv_bfloat162*>(Cb + (size_t)(row + 8) * NT + bn + coll) =
                        __floats2bfloat162_rn(a[2], a[3]);
            } else {
                float* Cf = (float*)Cv + (size_t)enc * NN * NT;
                if (row < M)
                    *reinterpret_cast<float2*>(Cf + (size_t)row * NT + bn + coll) =
                        make_float2(a[0], a[1]);
                if (row + 8 < M)
                    *reinterpret_cast<float2*>(Cf + (size_t)(row + 8) * NT + bn + coll) =
                        make_float2(a[2], a[3]);
            }
        }
    }

#pragma unroll
    for (int ni = 0; ni < 4; ni++) {
        float s0 = 0.f, s1 = 0.f, q0 = 0.f, q1 = 0.f;
#pragma unroll
        for (int mi = 0; mi < 4; mi++) {
            float* a = acc[mi][ni];
            s0 += a[0] + a[2];
            s1 += a[1] + a[3];
            q0 += a[0] * a[0] + a[2] * a[2];
            q1 += a[1] * a[1] + a[3] * a[3];
        }
#pragma unroll
        for (int off = 4; off < 32; off <<= 1) {
            s0 += __shfl_xor_sync(0xffffffff, s0, off);
            s1 += __shfl_xor_sync(0xffffffff, s1, off);
            q0 += __shfl_xor_sync(0xffffffff, q0, off);
            q1 += __shfl_xor_sync(0xffffffff, q1, off);
        }
        if (lane < 4) {
            int coll = nw * 32 + ni * 8 + 2 * fcol;
            atomicAdd(&ssum[coll], s0);
            atomicAdd(&ssum[coll + 1], s1);
            atomicAdd(&ssq[coll], q0);
            atomicAdd(&ssq[coll + 1], q1);
        }
    }
    __syncthreads();
    if (tid < 128) {
        atomicAdd(&stats_out[bn + tid], ssum[tid]);
        atomicAdd(&stats_out[NT + bn + tid], ssq[tid]);
    }
}

// ---------------- host orchestration ----------------

extern "C" void kernel_launch(void* const* d_in, const int* in_sizes, int n_in,
                              void* d_out, int out_size) {
    const float* feat       = (const float*)d_in[0];
    const int*   src        = (const int*)d_in[1];
    const int*   dst        = (const int*)d_in[2];
    const int*   graph_ids  = (const int*)d_in[3];
    const int*   mask_nodes = (const int*)d_in[4];
    const float* mask_token = (const float*)d_in[5];
    const float* enc_W1 = (const float*)d_in[6];
    const float* enc_g1 = (const float*)d_in[7];
    const float* enc_b1 = (const float*)d_in[8];
    const float* enc_W2 = (const float*)d_in[9];
    const float* enc_g2 = (const float*)d_in[10];
    const float* enc_b2 = (const float*)d_in[11];
    const float* con_W1 = (const float*)d_in[12];
    const float* con_g1 = (const float*)d_in[13];
    const float* con_b1 = (const float*)d_in[14];
    const float* con_W2 = (const float*)d_in[15];
    const float* con_g2 = (const float*)d_in[16];
    const float* con_b2 = (const float*)d_in[17];
    const float* pW1 = (const float*)d_in[18];
    const float* pb1 = (const float*)d_in[19];
    const float* pW2 = (const float*)d_in[20];
    const float* pb2 = (const float*)d_in[21];
    int nMask = in_sizes[4];

    float *pool, *statsArena, *p2, *z2;
    __nv_bfloat16 *xb, *hb, *z1b, *aggb;
    float *w1h, *w1l, *w2h, *w2l;
    int *rowptr, *cnt, *colidx;
    cudaGetSymbolAddress((void**)&xb, g_xb);
    cudaGetSymbolAddress((void**)&hb, g_hb);
    cudaGetSymbolAddress((void**)&z1b, g_z1b);
    cudaGetSymbolAddress((void**)&aggb, g_aggb);
    cudaGetSymbolAddress((void**)&z2, g_z2);
    cudaGetSymbolAddress((void**)&statsArena, g_statsArena);
    cudaGetSymbolAddress((void**)&pool, g_pool);
    cudaGetSymbolAddress((void**)&p2, g_p2);
    cudaGetSymbolAddress((void**)&w1h, g_W1T_hi);
    cudaGetSymbolAddress((void**)&w1l, g_W1T_lo);
    cudaGetSymbolAddress((void**)&w2h, g_W2T_hi);
    cudaGetSymbolAddress((void**)&w2l, g_W2T_lo);
    cudaGetSymbolAddress((void**)&rowptr, g_rowptr);
    cudaGetSymbolAddress((void**)&cnt, g_cnt);
    cudaGetSymbolAddress((void**)&colidx, g_col);

    cudaFuncSetAttribute(gemm_mma<0, HH, DD>, cudaFuncAttributeMaxDynamicSharedMemorySize, GEMM_SMEM);
    cudaFuncSetAttribute(gemm_mma<1, DD, HH>, cudaFuncAttributeMaxDynamicSharedMemorySize, GEMM_SMEM);

    // ---- prep ----
    cudaMemsetAsync(cnt, 0, NN * sizeof(int));
    count_kernel<<<(EE + 255) / 256, 256>>>(dst, cnt);
    scan_kernel<<<1, 1024>>>(cnt, rowptr);
    cudaMemsetAsync(cnt, 0, NN * sizeof(int));
    fill_kernel<<<(EE + 255) / 256, 256>>>(src, dst, rowptr, cnt, colidx);

    tsplit4<<<dim3((ENC_W + 255) / 256, 4), 256>>>(enc_W1, con_W1, enc_W2, con_W2,
                                                   w1h, w1l, w2h, w2l);

    conv_kernel<<<(NN * DD / 4 + 255) / 256, 256>>>(feat, xb, xb + (size_t)NN * DD);
    mask_kernel<<<(nMask * DD + 255) / 256, 256>>>(xb, mask_nodes, mask_token, nMask);

    cudaMemsetAsync(pool, 0, 2 * BB * LL * DD * sizeof(float));
    cudaMemsetAsync(statsArena, 0, 2 * LL * 2 * 512 * sizeof(float));
    cudaMemsetAsync(d_out, 0, sizeof(float));

    // ---- both encoders, batched per stage ----
    const int GB = (NN + 127) / 128;   // 391
    for (int l = 0; l < LL; l++) {
        const __nv_bfloat16* in0 = l == 0 ? xb : hb;
        const __nv_bfloat16* in1 = (l == 0 ? xb : hb) + (size_t)NN * DD;
        gather_kernel<<<dim3((NN * 32 + 255) / 256, 2), 256>>>(in0, in1, rowptr, colidx, aggb);

        float* st1 = statsArena + l * 1024;
        float* st2 = st1 + 512;
        gemm_mma<0, HH, DD><<<dim3(GB, HH / 128, 2), 256, GEMM_SMEM>>>(
            aggb, w1h + (size_t)l * HH * DD, w1l + (size_t)l * HH * DD,
            z1b, st1, nullptr, nullptr, nullptr, nullptr, nullptr, NN);
        gemm_mma<1, DD, HH><<<dim3(GB, 1, 2), 256, GEMM_SMEM>>>(
            z1b, w2h + (size_t)l * DD * HH, w2l + (size_t)l * DD * HH,
            z2, st2, st1,
            enc_g1 + l * HH, con_g1 + l * HH, enc_b1 + l * HH, con_b1 + l * HH, NN);

        bnrelu_pool<<<dim3((NN * DD / 4 + 255) / 256, 2), 256>>>(
            z2, st2, enc_g2 + l * DD, con_g2 + l * DD,
            enc_b2 + l * DD, con_b2 + l * DD, graph_ids, hb, pool, l * DD);
    }

    // ---- tail ----
    proj_kernel<<<dim3(BB, 2), 192>>>(pool, pW1, pb1, pW2, pb2, p2);
    loss_kernel<<<BB, 256>>>(p2 + BB * 128, p2, (float*)d_out);
}

// round 17
// speedup vs baseline: 1.1553x; 1.0983x over previous
#include <cuda_runtime.h>
#include <cuda_bf16.h>
#include <math.h>
#include <stdint.h>

#define NN 50000
#define EE 800000
#define BB 256
#define DD 128
#define HH 256
#define LL 3
#define TEMP 0.2f
#define BN_EPS 1e-5f

// ---------------- scratch (device globals) ----------------
__device__ __align__(16) __nv_bfloat16 g_xb[2][(size_t)NN * DD];
__device__ __align__(16) __nv_bfloat16 g_hb[2][(size_t)NN * DD];
__device__ __align__(16) __nv_bfloat16 g_z1b[2][(size_t)NN * HH];
__device__ __align__(16) __nv_bfloat16 g_aggb[2][(size_t)NN * DD];
__device__ __align__(16) float g_z2[2][(size_t)NN * DD];
__device__ __align__(16) float g_statsArena[2 * LL * 2 * 512];
__device__ __align__(16) float g_pool[2 * BB * LL * DD];
__device__ __align__(16) float g_p2[2 * BB * 128];
__device__ __align__(16) float g_W1T_hi[2 * LL * HH * DD];
__device__ __align__(16) float g_W1T_lo[2 * LL * HH * DD];
__device__ __align__(16) float g_W2T_hi[2 * LL * DD * HH];
__device__ __align__(16) float g_W2T_lo[2 * LL * DD * HH];
__device__ int g_rowptr[NN + 1];
__device__ int g_cnt[NN];
__device__ int g_col[EE];

#define ENC_W (LL * DD * HH)
#define ENC_ST (LL * 1024)

// ---------------- helpers ----------------
__device__ __forceinline__ float tf32_round(float x) {
    uint32_t u;
    asm("cvt.rna.tf32.f32 %0, %1;" : "=r"(u) : "f"(x));
    return __uint_as_float(u);
}
__device__ __forceinline__ void red_add_v4(float* p, float4 v) {
    asm volatile("red.global.add.v4.f32 [%0], {%1,%2,%3,%4};"
                 :: "l"(p), "f"(v.x), "f"(v.y), "f"(v.z), "f"(v.w) : "memory");
}
__device__ __forceinline__ void mma_tf32(float* c, const uint32_t* a, const uint32_t* b) {
    asm volatile(
        "mma.sync.aligned.m16n8k8.row.col.f32.tf32.tf32.f32 "
        "{%0,%1,%2,%3}, {%4,%5,%6,%7}, {%8,%9}, {%0,%1,%2,%3};"
        : "+f"(c[0]), "+f"(c[1]), "+f"(c[2]), "+f"(c[3])
        : "r"(a[0]), "r"(a[1]), "r"(a[2]), "r"(a[3]), "r"(b[0]), "r"(b[1]));
}
__device__ __forceinline__ uint32_t smem_u32(const void* p) {
    uint32_t a;
    asm("{ .reg .u64 t; cvta.to.shared.u64 t, %1; cvt.u32.u64 %0, t; }" : "=r"(a) : "l"(p));
    return a;
}
__device__ __forceinline__ void cpa16(uint32_t dst, const float* src) {
    asm volatile("cp.async.ca.shared.global [%0], [%1], 16;"
                 :: "r"(dst), "l"(src) : "memory");
}
#define CPA_COMMIT() asm volatile("cp.async.commit_group;" ::: "memory")
#define CPA_WAIT(n)  asm volatile("cp.async.wait_group %0;" :: "n"(n) : "memory")

__device__ __forceinline__ float4 bf8_to_f4(uint2 u) {
    __nv_bfloat162 b0 = *reinterpret_cast<__nv_bfloat162*>(&u.x);
    __nv_bfloat162 b1 = *reinterpret_cast<__nv_bfloat162*>(&u.y);
    float2 f0 = __bfloat1622float2(b0);
    float2 f1 = __bfloat1622float2(b1);
    return make_float4(f0.x, f0.y, f1.x, f1.y);
}
__device__ __forceinline__ uint2 f4_to_bf8(float4 v) {
    __nv_bfloat162 p0 = __floats2bfloat162_rn(v.x, v.y);
    __nv_bfloat162 p1 = __floats2bfloat162_rn(v.z, v.w);
    uint2 u;
    u.x = *reinterpret_cast<uint32_t*>(&p0);
    u.y = *reinterpret_cast<uint32_t*>(&p1);
    return u;
}

// ---------------- CSR build ----------------
__global__ void count_kernel(const int* __restrict__ dst, int* __restrict__ cnt) {
    int e = blockIdx.x * blockDim.x + threadIdx.x;
    if (e < EE) atomicAdd(&cnt[dst[e]], 1);
}

__global__ void scan_kernel(const int* __restrict__ cnt, int* __restrict__ rowptr) {
    __shared__ int wsums[32];
    __shared__ int s_carry;
    int t = threadIdx.x, lane = t & 31, w = t >> 5;
    if (t == 0) s_carry = 0;
    __syncthreads();
    for (int base = 0; base < NN; base += 1024) {
        int i = base + t;
        int v = (i < NN) ? cnt[i] : 0;
        int x = v;
#pragma unroll
        for (int o = 1; o < 32; o <<= 1) {
            int y = __shfl_up_sync(0xffffffff, x, o);
            if (lane >= o) x += y;
        }
        if (lane == 31) wsums[w] = x;
        __syncthreads();
        if (w == 0) {
            int s = wsums[lane];
#pragma unroll
            for (int o = 1; o < 32; o <<= 1) {
                int y = __shfl_up_sync(0xffffffff, s, o);
                if (lane >= o) s += y;
            }
            wsums[lane] = s;
        }
        __syncthreads();
        int excl = x - v + (w ? wsums[w - 1] : 0) + s_carry;
        if (i < NN) rowptr[i] = excl;
        __syncthreads();
        if (t == 1023) s_carry += x + wsums[30];
        __syncthreads();
    }
    if (t == 0) rowptr[NN] = s_carry;
}

__global__ void fill_kernel(const int* __restrict__ src, const int* __restrict__ dst,
                            const int* __restrict__ rowptr, int* __restrict__ cnt,
                            int* __restrict__ col) {
    int e = blockIdx.x * blockDim.x + threadIdx.x;
    if (e >= EE) return;
    int d = dst[e];
    int pos = __ldg(rowptr + d) + atomicAdd(&cnt[d], 1);
    col[pos] = src[e];
}

// ---- gather (bf16 in, bf16 out): agg[n] = h[n] + sum_{m} h[m] (fp32 acc) ----
__global__ void gather_kernel(const __nv_bfloat16* __restrict__ hin0,
                              const __nv_bfloat16* __restrict__ hin1,
                              const int* __restrict__ rowptr, const int* __restrict__ col,
                              __nv_bfloat16* __restrict__ aggb) {
    int enc = blockIdx.y;
    const __nv_bfloat16* hin = enc ? hin1 : hin0;
    aggb += (size_t)enc * NN * DD;
    int wid = (blockIdx.x * blockDim.x + threadIdx.x) >> 5;
    if (wid >= NN) return;
    int lane = threadIdx.x & 31;
    int r0 = __ldg(rowptr + wid), r1 = __ldg(rowptr + wid + 1);
    float4 acc = bf8_to_f4(*reinterpret_cast<const uint2*>(hin + (size_t)wid * DD + lane * 4));
    for (int base = r0; base < r1; base += 32) {
        int idx = (base + lane < r1) ? __ldg(col + base + lane) : 0;
        int m = min(32, r1 - base);
        int j = 0;
        for (; j + 4 <= m; j += 4) {
            int n0 = __shfl_sync(0xffffffff, idx, j);
            int n1 = __shfl_sync(0xffffffff, idx, j + 1);
            int n2 = __shfl_sync(0xffffffff, idx, j + 2);
            int n3 = __shfl_sync(0xffffffff, idx, j + 3);
            uint2 u0 = *reinterpret_cast<const uint2*>(hin + (size_t)n0 * DD + lane * 4);
            uint2 u1 = *reinterpret_cast<const uint2*>(hin + (size_t)n1 * DD + lane * 4);
            uint2 u2 = *reinterpret_cast<const uint2*>(hin + (size_t)n2 * DD + lane * 4);
            uint2 u3 = *reinterpret_cast<const uint2*>(hin + (size_t)n3 * DD + lane * 4);
            float4 v0 = bf8_to_f4(u0);
            float4 v1 = bf8_to_f4(u1);
            float4 v2 = bf8_to_f4(u2);
            float4 v3 = bf8_to_f4(u3);
            acc.x += v0.x + v1.x + v2.x + v3.x;
            acc.y += v0.y + v1.y + v2.y + v3.y;
            acc.z += v0.z + v1.z + v2.z + v3.z;
            acc.w += v0.w + v1.w + v2.w + v3.w;
        }
        for (; j < m; j++) {
            int n = __shfl_sync(0xffffffff, idx, j);
            float4 v = bf8_to_f4(*reinterpret_cast<const uint2*>(hin + (size_t)n * DD + lane * 4));
            acc.x += v.x; acc.y += v.y; acc.z += v.z; acc.w += v.w;
        }
    }
    *reinterpret_cast<uint2*>(aggb + (size_t)wid * DD + lane * 4) = f4_to_bf8(acc);
}

// ---------------- small kernels ----------------
__global__ void conv_kernel(const float* __restrict__ feat,
                            __nv_bfloat16* __restrict__ xb0,
                            __nv_bfloat16* __restrict__ xb1) {
    int idx = blockIdx.x * blockDim.x + threadIdx.x;
    if (idx >= NN * DD / 4) return;
    float4 v = reinterpret_cast<const float4*>(feat)[idx];
    uint2 u = f4_to_bf8(v);
    *reinterpret_cast<uint2*>(xb0 + (size_t)idx * 4) = u;
    *reinterpret_cast<uint2*>(xb1 + (size_t)idx * 4) = u;
}

__global__ void mask_kernel(__nv_bfloat16* __restrict__ x, const int* __restrict__ idx,
                            const float* __restrict__ tok, int nMask) {
    int i = blockIdx.x * blockDim.x + threadIdx.x;
    if (i >= nMask * DD) return;
    int m = i >> 7, c = i & 127;
    x[(size_t)idx[m] * DD + c] = __float2bfloat16_rn(tok[c]);
}

__global__ void bnrelu_pool(const float* __restrict__ Z, const float* __restrict__ stats,
                            const float* __restrict__ g0, const float* __restrict__ g1,
                            const float* __restrict__ b0, const float* __restrict__ b1,
                            const int* __restrict__ gid, __nv_bfloat16* __restrict__ hb,
                            float* __restrict__ pool, int colOff) {
    int enc = blockIdx.y;
    Z += (size_t)enc * NN * DD;
    hb += (size_t)enc * NN * DD;
    stats += (size_t)enc * ENC_ST;
    pool += (size_t)enc * BB * LL * DD;
    const float* g = enc ? g1 : g0;
    const float* b = enc ? b1 : b0;

    __shared__ __align__(16) float sab[2 * DD];
    int t = threadIdx.x;
    if (t < DD) {
        float m = stats[t] * (1.0f / NN);
        float var = stats[DD + t] * (1.0f / NN) - m * m;
        float a = g[t] * rsqrtf(var + BN_EPS);
        sab[t] = a;
        sab[DD + t] = b[t] - m * a;
    }
    __syncthreads();
    int idx = blockIdx.x * blockDim.x + t;
    if (idx >= NN * DD / 4) return;
    int r = idx >> 5;
    int c = (idx & 31) * 4;
    float4 z = *reinterpret_cast<const float4*>(Z + (size_t)idx * 4);
    float4 sa = *reinterpret_cast<const float4*>(sab + c);
    float4 sc = *reinterpret_cast<const float4*>(sab + DD + c);
    float4 v;
    v.x = fmaxf(fmaf(z.x, sa.x, sc.x), 0.f);
    v.y = fmaxf(fmaf(z.y, sa.y, sc.y), 0.f);
    v.z = fmaxf(fmaf(z.z, sa.z, sc.z), 0.f);
    v.w = fmaxf(fmaf(z.w, sa.w, sc.w), 0.f);
    *reinterpret_cast<uint2*>(hb + (size_t)idx * 4) = f4_to_bf8(v);
    red_add_v4(&pool[(size_t)gid[r] * (LL * DD) + colOff + c], v);
}

__global__ void proj_kernel(const float* __restrict__ pool, const float* __restrict__ pW1,
                            const float* __restrict__ pb1, const float* __restrict__ pW2,
                            const float* __restrict__ pb2, float* __restrict__ out) {
    __shared__ float row[LL * DD];
    __shared__ float h1[192];
    int i = blockIdx.x + blockIdx.y * BB;
    int t = threadIdx.x;
    for (int k = t; k < LL * DD; k += 192) row[k] = pool[(size_t)i * (LL * DD) + k];
    __syncthreads();
    float s = pb1[t];
    for (int k = 0; k < LL * DD; k++) s += row[k] * pW1[(size_t)k * 192 + t];
    h1[t] = fmaxf(s, 0.f);
    __syncthreads();
    if (t < 128) {
        float s2 = pb2[t];
        for (int k = 0; k < 192; k++) s2 += h1[k] * pW2[(size_t)k * 128 + t];
        out[(size_t)i * 128 + t] = s2;
    }
}

// loss with norms computed inline
__global__ void loss_kernel(const float* __restrict__ ch, const float* __restrict__ cm,
                            float* __restrict__ out) {
    int i = blockIdx.x;
    int t = threadIdx.x;
    __shared__ float sh[128];
    __shared__ float red[256];
    __shared__ float posv;
    if (t < 128) sh[t] = ch[(size_t)i * 128 + t];
    __syncthreads();
    const float* rowj = cm + (size_t)t * 128;
    float d = 0.f, q = 0.f, p = 0.f;
    for (int k = 0; k < 128; k++) {
        float a = sh[k], bq = rowj[k];
        d = fmaf(a, bq, d);
        q = fmaf(bq, bq, q);
        p = fmaf(a, a, p);
    }
    float s = expf(d / (sqrtf(p) * sqrtf(q)) * (1.0f / TEMP));
    if (t == i) posv = s;
    red[t] = s;
    __syncthreads();
    for (int o = 128; o; o >>= 1) {
        if (t < o) red[t] += red[t + o];
        __syncthreads();
    }
    if (t == 0) {
        float sum = red[0];
        float li = -logf(posv / (sum - posv));
        atomicAdd(out, li * (1.0f / BB));
    }
}

__global__ void tsplit4(const float* __restrict__ W1e, const float* __restrict__ W1c,
                        const float* __restrict__ W2e, const float* __restrict__ W2c,
                        float* __restrict__ w1h, float* __restrict__ w1l,
                        float* __restrict__ w2h, float* __restrict__ w2l) {
    int which = blockIdx.y;
    const float* W;
    float *hi, *lo;
    int K, N;
    if (which == 0)      { W = W1e; hi = w1h;         lo = w1l;         K = DD; N = HH; }
    else if (which == 1) { W = W1c; hi = w1h + ENC_W; lo = w1l + ENC_W; K = DD; N = HH; }
    else if (which == 2) { W = W2e; hi = w2h;         lo = w2l;         K = HH; N = DD; }
    else                 { W = W2c; hi = w2h + ENC_W; lo = w2l + ENC_W; K = HH; N = DD; }
    int i = blockIdx.x * blockDim.x + threadIdx.x;
    if (i >= ENC_W) return;
    int l = i / (K * N), rem = i % (K * N);
    int k = rem / N, n = rem % N;
    float v = W[i];
    float h = tf32_round(v);
    size_t o = (size_t)l * K * N + (size_t)n * K + k;
    hi[o] = h;
    lo[o] = v - h;
}

// ---- 2xTF32 mma.sync GEMM, cp.async double-buffered B, register-staged A ----
// A bf16 both modes. MODE 0: plain A (agg), C bf16 (z1).
// MODE 1: A=z1 + fused BN+ReLU, C fp32 (z2). OOB rows contribute 0 to stats.
#define PAD 36
#define CHUNK_F (128 * PAD)
#define GEMM_SMEM ((5 * CHUNK_F + 2 * 256) * 4)   // 94208 B

template <int MODE, int NT, int KT>
__global__ __launch_bounds__(256, 2)
void gemm_mma(const __nv_bfloat16* __restrict__ Ab, const float* __restrict__ Bh,
              const float* __restrict__ Bl, void* __restrict__ Cv,
              float* __restrict__ stats_out, const float* __restrict__ stats_in,
              const float* __restrict__ g0, const float* __restrict__ g1,
              const float* __restrict__ b0, const float* __restrict__ b1, int M) {
    const int enc = blockIdx.z;
    Bh += (size_t)enc * ENC_W;
    Bl += (size_t)enc * ENC_W;
    stats_out += (size_t)enc * ENC_ST;
    const float* g = enc ? g1 : g0;
    const float* b = enc ? b1 : b0;

    extern __shared__ float sm[];
    float* As = sm;                          // [128][PAD]
    float* Bbuf[2][2];                       // [buf][hi/lo]
    Bbuf[0][0] = As + CHUNK_F;
    Bbuf[0][1] = As + 2 * CHUNK_F;
    Bbuf[1][0] = As + 3 * CHUNK_F;
    Bbuf[1][1] = As + 4 * CHUNK_F;
    float* sab = As + 5 * CHUNK_F;           // [2*KT]
    __shared__ float ssum[128], ssq[128];

    const int tid = threadIdx.x;
    const int lane = tid & 31, w = tid >> 5;
    const int mw = w >> 2, nw = w & 3;
    const int bm = blockIdx.x * 128, bn = blockIdx.y * 128;

    if (MODE == 1) {
        const float* si = stats_in + (size_t)enc * ENC_ST;
        for (int i = tid; i < KT; i += 256) {
            float m = si[i] * (1.0f / NN);
            float var = si[KT + i] * (1.0f / NN) - m * m;
            float a = g[i] * rsqrtf(var + BN_EPS);
            sab[i] = a;
            sab[KT + i] = b[i] - m * a;
        }
    }
    __syncthreads();   // sab ready before first commitA (MODE 1)

    float acc[4][4][4];
#pragma unroll
    for (int mi = 0; mi < 4; mi++)
#pragma unroll
        for (int ni = 0; ni < 4; ni++)
#pragma unroll
            for (int r = 0; r < 4; r++) acc[mi][ni][r] = 0.f;

    const int lrow = tid >> 1;
    const int lcol0 = (tid & 1) * 16;
    const bool rok = (bm + lrow) < M;
    const __nv_bfloat16* ArowB = Ab + (size_t)enc * NN * KT + (size_t)(bm + lrow) * KT;

    const int frow = lane >> 2;
    const int fcol = lane & 3;
    constexpr int NC = KT / 32;

    // B issue: 128 rows x 32 fp32 cols, hi+lo, 8 cp.async per thread
    const uint32_t sb = smem_u32(sm);
    auto issueB = [&](int c, int buf) {
        uint32_t dh = sb + (uint32_t)((1 + 2 * buf) * CHUNK_F) * 4;
        uint32_t dl = dh + (uint32_t)CHUNK_F * 4;
#pragma unroll
        for (int i = 0; i < 4; i++) {
            int seg = tid + i * 256;          // 0..1023
            int row = seg >> 3, qd = seg & 7;
            uint32_t off = (uint32_t)(row * PAD * 4 + qd * 16);
            cpa16(dh + off, Bh + (size_t)(bn + row) * KT + c * 32 + qd * 4);
            cpa16(dl + off, Bl + (size_t)(bn + row) * KT + c * 32 + qd * 4);
        }
        CPA_COMMIT();
    };

    uint4 ua[2];
    auto stageA = [&](int c) {
#pragma unroll
        for (int half = 0; half < 2; half++)
            ua[half] = rok ? *reinterpret_cast<const uint4*>(ArowB + c * 32 + lcol0 + half * 8)
                           : make_uint4(0, 0, 0, 0);
    };
    auto commitA = [&]() {
#pragma unroll
        for (int half = 0; half < 2; half++) {
            uint32_t uu[4] = {ua[half].x, ua[half].y, ua[half].z, ua[half].w};
#pragma unroll
            for (int j = 0; j < 4; j++) {
                __nv_bfloat162 bb = *reinterpret_cast<__nv_bfloat162*>(&uu[j]);
                float2 f = __bfloat1622float2(bb);
                int col = lcol0 + half * 8 + j * 2;
                float a0, a1;
                if (MODE == 1) {
                    a0 = rok ? fmaxf(fmaf(f.x, sab[col], sab[KT + col]), 0.f) : 0.f;
                    a1 = rok ? fmaxf(fmaf(f.y, sab[col + 1], sab[KT + col + 1]), 0.f) : 0.f;
                } else {
                    a0 = f.x;
                    a1 = f.y;
                }
                As[lrow * PAD + col] = tf32_round(a0);
                As[lrow * PAD + col + 1] = tf32_round(a1);
            }
        }
    };

    // prologue
    issueB(0, 0);
    if (NC > 1) issueB(1, 1);
    stageA(0);

    for (int c = 0; c < NC; c++) {
        commitA();
        if (c + 1 < NC) stageA(c + 1);
        if (c < NC - 1) { CPA_WAIT(1); } else { CPA_WAIT(0); }
        __syncthreads();

        float* Bhs = Bbuf[c & 1][0];
        float* Bls = Bbuf[c & 1][1];
#pragma unroll
        for (int kk = 0; kk < 4; kk++) {
            const int k = kk * 8;
            uint32_t af[4][4];
#pragma unroll
            for (int mi = 0; mi < 4; mi++) {
                int r0 = mw * 64 + mi * 16 + frow;
                int c0 = k + fcol;
                af[mi][0] = __float_as_uint(As[r0 * PAD + c0]);
                af[mi][1] = __float_as_uint(As[(r0 + 8) * PAD + c0]);
                af[mi][2] = __float_as_uint(As[r0 * PAD + c0 + 4]);
                af[mi][3] = __float_as_uint(As[(r0 + 8) * PAD + c0 + 4]);
            }
            uint32_t bfh[4][2], bfl[4][2];
#pragma unroll
            for (int ni = 0; ni < 4; ni++) {
                int n0 = nw * 32 + ni * 8 + frow;
                int kb = k + fcol;
                bfh[ni][0] = __float_as_uint(Bhs[n0 * PAD + kb]);
                bfh[ni][1] = __float_as_uint(Bhs[n0 * PAD + kb + 4]);
                bfl[ni][0] = __float_as_uint(Bls[n0 * PAD + kb]);
                bfl[ni][1] = __float_as_uint(Bls[n0 * PAD + kb + 4]);
            }
#pragma unroll
            for (int mi = 0; mi < 4; mi++)
#pragma unroll
                for (int ni = 0; ni < 4; ni++) {
                    mma_tf32(acc[mi][ni], af[mi], bfh[ni]);
                    mma_tf32(acc[mi][ni], af[mi], bfl[ni]);
                }
        }
        __syncthreads();
        if (c + 2 < NC) issueB(c + 2, c & 1);
    }

    // ---- epilogue: C store + fused column stats ----
    if (tid < 128) { ssum[tid] = 0.f; ssq[tid] = 0.f; }
    __syncthreads();

#pragma unroll
    for (int mi = 0; mi < 4; mi++) {
#pragma unroll
        for (int ni = 0; ni < 4; ni++) {
            int row = bm + mw * 64 + mi * 16 + frow;
            int coll = nw * 32 + ni * 8 + 2 * fcol;
            float* a = acc[mi][ni];
            if (MODE == 0) {
                __nv_bfloat16* Cb = (__nv_bfloat16*)Cv + (size_t)enc * NN * NT;
                if (row < M)
                    *reinterpret_cast<__nv_bfloat162*>(Cb + (size_t)row * NT + bn + coll) =
                        __floats2bfloat162_rn(a[0], a[1]);
                if (row + 8 < M)
                    *reinterpret_cast<__nv_bfloat162*>(Cb + (size_t)(row + 8) * NT + bn + coll) =
                        __floats2bfloat162_rn(a[2], a[3]);
            } else {
                float* Cf = (float*)Cv + (size_t)enc * NN * NT;
                if (row < M)
                    *reinterpret_cast<float2*>(Cf + (size_t)row * NT + bn + coll) =
                        make_float2(a[0], a[1]);
                if (row + 8 < M)
                    *reinterpret_cast<float2*>(Cf + (size_t)(row + 8) * NT + bn + coll) =
                        make_float2(a[2], a[3]);
            }
        }
    }

#pragma unroll
    for (int ni = 0; ni < 4; ni++) {
        float s0 = 0.f, s1 = 0.f, q0 = 0.f, q1 = 0.f;
#pragma unroll
        for (int mi = 0; mi < 4; mi++) {
            float* a = acc[mi][ni];
            s0 += a[0] + a[2];
            s1 += a[1] + a[3];
            q0 += a[0] * a[0] + a[2] * a[2];
            q1 += a[1] * a[1] + a[3] * a[3];
        }
#pragma unroll
        for (int off = 4; off < 32; off <<= 1) {
            s0 += __shfl_xor_sync(0xffffffff, s0, off);
            s1 += __shfl_xor_sync(0xffffffff, s1, off);
            q0 += __shfl_xor_sync(0xffffffff, q0, off);
            q1 += __shfl_xor_sync(0xffffffff, q1, off);
        }
        if (lane < 4) {
            int coll = nw * 32 + ni * 8 + 2 * fcol;
            atomicAdd(&ssum[coll], s0);
            atomicAdd(&ssum[coll + 1], s1);
            atomicAdd(&ssq[coll], q0);
            atomicAdd(&ssq[coll + 1], q1);
        }
    }
    __syncthreads();
    if (tid < 128) {
        atomicAdd(&stats_out[bn + tid], ssum[tid]);
        atomicAdd(&stats_out[NT + bn + tid], ssq[tid]);
    }
}

// ---------------- host orchestration ----------------

extern "C" void kernel_launch(void* const* d_in, const int* in_sizes, int n_in,
                              void* d_out, int out_size) {
    const float* feat       = (const float*)d_in[0];
    const int*   src        = (const int*)d_in[1];
    const int*   dst        = (const int*)d_in[2];
    const int*   graph_ids  = (const int*)d_in[3];
    const int*   mask_nodes = (const int*)d_in[4];
    const float* mask_token = (const float*)d_in[5];
    const float* enc_W1 = (const float*)d_in[6];
    const float* enc_g1 = (const float*)d_in[7];
    const float* enc_b1 = (const float*)d_in[8];
    const float* enc_W2 = (const float*)d_in[9];
    const float* enc_g2 = (const float*)d_in[10];
    const float* enc_b2 = (const float*)d_in[11];
    const float* con_W1 = (const float*)d_in[12];
    const float* con_g1 = (const float*)d_in[13];
    const float* con_b1 = (const float*)d_in[14];
    const float* con_W2 = (const float*)d_in[15];
    const float* con_g2 = (const float*)d_in[16];
    const float* con_b2 = (const float*)d_in[17];
    const float* pW1 = (const float*)d_in[18];
    const float* pb1 = (const float*)d_in[19];
    const float* pW2 = (const float*)d_in[20];
    const float* pb2 = (const float*)d_in[21];
    int nMask = in_sizes[4];

    float *pool, *statsArena, *p2, *z2;
    __nv_bfloat16 *xb, *hb, *z1b, *aggb;
    float *w1h, *w1l, *w2h, *w2l;
    int *rowptr, *cnt, *colidx;
    cudaGetSymbolAddress((void**)&xb, g_xb);
    cudaGetSymbolAddress((void**)&hb, g_hb);
    cudaGetSymbolAddress((void**)&z1b, g_z1b);
    cudaGetSymbolAddress((void**)&aggb, g_aggb);
    cudaGetSymbolAddress((void**)&z2, g_z2);
    cudaGetSymbolAddress((void**)&statsArena, g_statsArena);
    cudaGetSymbolAddress((void**)&pool, g_pool);
    cudaGetSymbolAddress((void**)&p2, g_p2);
    cudaGetSymbolAddress((void**)&w1h, g_W1T_hi);
    cudaGetSymbolAddress((void**)&w1l, g_W1T_lo);
    cudaGetSymbolAddress((void**)&w2h, g_W2T_hi);
    cudaGetSymbolAddress((void**)&w2l, g_W2T_lo);
    cudaGetSymbolAddress((void**)&rowptr, g_rowptr);
    cudaGetSymbolAddress((void**)&cnt, g_cnt);
    cudaGetSymbolAddress((void**)&colidx, g_col);

    cudaFuncSetAttribute(gemm_mma<0, HH, DD>, cudaFuncAttributeMaxDynamicSharedMemorySize, GEMM_SMEM);
    cudaFuncSetAttribute(gemm_mma<1, DD, HH>, cudaFuncAttributeMaxDynamicSharedMemorySize, GEMM_SMEM);

    // ---- prep ----
    cudaMemsetAsync(cnt, 0, NN * sizeof(int));
    count_kernel<<<(EE + 255) / 256, 256>>>(dst, cnt);
    scan_kernel<<<1, 1024>>>(cnt, rowptr);
    cudaMemsetAsync(cnt, 0, NN * sizeof(int));
    fill_kernel<<<(EE + 255) / 256, 256>>>(src, dst, rowptr, cnt, colidx);

    tsplit4<<<dim3((ENC_W + 255) / 256, 4), 256>>>(enc_W1, con_W1, enc_W2, con_W2,
                                                   w1h, w1l, w2h, w2l);

    conv_kernel<<<(NN * DD / 4 + 255) / 256, 256>>>(feat, xb, xb + (size_t)NN * DD);
    mask_kernel<<<(nMask * DD + 255) / 256, 256>>>(xb, mask_nodes, mask_token, nMask);

    cudaMemsetAsync(pool, 0, 2 * BB * LL * DD * sizeof(float));
    cudaMemsetAsync(statsArena, 0, 2 * LL * 2 * 512 * sizeof(float));
    cudaMemsetAsync(d_out, 0, sizeof(float));

    // ---- both encoders, batched per stage ----
    const int GB = (NN + 127) / 128;   // 391
    for (int l = 0; l < LL; l++) {
        const __nv_bfloat16* in0 = l == 0 ? xb : hb;
        const __nv_bfloat16* in1 = (l == 0 ? xb : hb) + (size_t)NN * DD;
        gather_kernel<<<dim3((NN * 32 + 255) / 256, 2), 256>>>(in0, in1, rowptr, colidx, aggb);

        float* st1 = statsArena + l * 1024;
        float* st2 = st1 + 512;
        gemm_mma<0, HH, DD><<<dim3(GB, HH / 128, 2), 256, GEMM_SMEM>>>(
            aggb, w1h + (size_t)l * HH * DD, w1l + (size_t)l * HH * DD,
            z1b, st1, nullptr, nullptr, nullptr, nullptr, nullptr, NN);
        gemm_mma<1, DD, HH><<<dim3(GB, 1, 2), 256, GEMM_SMEM>>>(
            z1b, w2h + (size_t)l * DD * HH, w2l + (size_t)l * DD * HH,
            z2, st2, st1,
            enc_g1 + l * HH, con_g1 + l * HH, enc_b1 + l * HH, con_b1 + l * HH, NN);

        bnrelu_pool<<<dim3((NN * DD / 4 + 255) / 256, 2), 256>>>(
            z2, st2, enc_g2 + l * DD, con_g2 + l * DD,
            enc_b2 + l * DD, con_b2 + l * DD, graph_ids, hb, pool, l * DD);
    }

    // ---- tail ----
    proj_kernel<<<dim3(BB, 2), 192>>>(pool, pW1, pb1, pW2, pb2, p2);
    loss_kernel<<<BB, 256>>>(p2 + BB * 128, p2, (float*)d_out);
}